// round 16
// baseline (speedup 1.0000x reference)
#include <cuda_runtime.h>
#include <cstdint>

#define BB     8
#define NPTS   8192
#define NBIN   1024
#define RANGE_LO (-6.5f)
#define BW       (13.0f / NBIN)      // 0.0126953125
#define INV_BW   (1.0f / BW)
#define NSLOTS   64
#define PAD0     6                   // initial window pad (bins)
#define CHUNK    8                   // expansion step (bins)

// ---- scratch (no allocations allowed) ----
__device__ float4   g_sx[2][BB][NPTS];        // x-sorted points (x,y,z,|p|^2)
__device__ unsigned g_bcnt[2][BB][NBIN];      // per-bin counts
__device__ unsigned g_bstart[2][BB][NBIN + 1];// exclusive starts (+ total sentinel)
__device__ unsigned g_bfill[2][BB][NBIN];     // scatter cursors
__device__ double   g_part[2][NSLOTS];        // spread partial sums

__device__ __forceinline__ int bin_of(float v) {
    int c = (int)((v - RANGE_LO) * INV_BW);
    return min(max(c, 0), NBIN - 1);
}

// ---- zero counters/accumulators ----
__global__ void zero_kernel() {
    int i = blockIdx.x * blockDim.x + threadIdx.x;
    if (i < 2 * BB * NBIN) {
        ((unsigned*)g_bcnt)[i] = 0u;
        ((unsigned*)g_bfill)[i] = 0u;
    }
    if (i < 2 * NSLOTS) ((double*)g_part)[i] = 0.0;
}

// ---- histogram over x-bins ----
__global__ void hist_kernel(const float* __restrict__ pred, const float* __restrict__ targ) {
    int i = blockIdx.x * blockDim.x + threadIdx.x;
    if (i >= 2 * BB * NPTS) return;
    int cloud = i / (BB * NPTS);
    int rem = i - cloud * (BB * NPTS);
    const float* src = cloud ? targ : pred;
    float x = src[3 * rem];
    int b = rem / NPTS;
    atomicAdd(&g_bcnt[cloud][b][bin_of(x)], 1u);
}

// ---- exclusive scan over 1024 bins per (cloud,batch) ----
__global__ void scan_kernel() {
    int inst = blockIdx.x;               // 0..15
    int cloud = inst >> 3, b = inst & 7;
    int t = threadIdx.x;                 // 1024 threads = 1 bin each
    unsigned c = g_bcnt[cloud][b][t];
    __shared__ unsigned sh[NBIN];
    sh[t] = c;
    __syncthreads();
    for (int o = 1; o < NBIN; o <<= 1) {
        unsigned v = (t >= o) ? sh[t - o] : 0u;
        __syncthreads();
        sh[t] += v;
        __syncthreads();
    }
    g_bstart[cloud][b][t] = sh[t] - c;   // exclusive
    if (t == NBIN - 1) g_bstart[cloud][b][NBIN] = sh[t];
}

// ---- scatter into bin-sorted order (store |p|^2 in w) ----
__global__ void scatter_kernel(const float* __restrict__ pred, const float* __restrict__ targ) {
    int i = blockIdx.x * blockDim.x + threadIdx.x;
    if (i >= 2 * BB * NPTS) return;
    int cloud = i / (BB * NPTS);
    int rem = i - cloud * (BB * NPTS);
    const float* src = cloud ? targ : pred;
    float x = src[3 * rem], y = src[3 * rem + 1], z = src[3 * rem + 2];
    int b = rem / NPTS;
    int bn = bin_of(x);
    unsigned pos = g_bstart[cloud][b][bn] + atomicAdd(&g_bfill[cloud][b][bn], 1u);
    g_sx[cloud][b][pos] = make_float4(x, y, z, x * x + y * y + z * z);
}

// ---- exact NN via 1D sorted sliding window ----
// Warp = 32 consecutive x-sorted queries (lane = query, coalesced load; full
// lane utilization always). Candidates = contiguous span covering bin window
// [blo,bhi]; broadcast-streamed, 4 fp32 + 1 min per candidate serving 32
// queries. Exact bound: any point in bins < blo has x <= left_edge(blo), so
// dist >= (qx - left_edge)^2; same on the right (bin-edge bound is immune to
// within-bin disorder). Expand by CHUNK bins per needed side until every lane
// satisfies its bound; at array ends the side is exhausted (no points remain).
__global__ void __launch_bounds__(256) query_kernel() {
    int wq = blockIdx.x * 8 + (threadIdx.x >> 5);   // 4096 warps total
    int lane = threadIdx.x & 31;
    int cloud = (wq >> 11) & 1;
    int b = (wq >> 8) & 7;
    int qidx = (wq & 255) * 32 + lane;

    float4 q = g_sx[cloud][b][qidx];                 // coalesced
    const float4*   __restrict__ Pc = g_sx[cloud ^ 1][b];
    const unsigned* __restrict__ S  = g_bstart[cloud ^ 1][b];

    const float m2x = -2.f * q.x, m2y = -2.f * q.y, m2z = -2.f * q.z, qw = q.w;
    float best = INFINITY;

#define SCAN_SPAN(I0, I1) do {                                                  \
        unsigned i_ = (I0), e_ = (I1);                                          \
        for (; i_ + 2 <= e_; i_ += 2) {                                         \
            float4 p0_ = Pc[i_], p1_ = Pc[i_ + 1];                              \
            float d0_ = fmaf(m2x, p0_.x, fmaf(m2y, p0_.y, fmaf(m2z, p0_.z, qw + p0_.w))); \
            float d1_ = fmaf(m2x, p1_.x, fmaf(m2y, p1_.y, fmaf(m2z, p1_.z, qw + p1_.w))); \
            best = fminf(best, fminf(d0_, d1_));                                \
        }                                                                       \
        if (i_ < e_) {                                                          \
            float4 p0_ = Pc[i_];                                                \
            best = fminf(best, fmaf(m2x, p0_.x, fmaf(m2y, p0_.y, fmaf(m2z, p0_.z, qw + p0_.w)))); \
        }                                                                       \
    } while (0)

    // initial window: warp's bin range +- PAD0
    int qbin = bin_of(q.x);
    int blo = max((int)__reduce_min_sync(0xFFFFFFFFu, (unsigned)qbin) - PAD0, 0);
    int bhi = min((int)__reduce_max_sync(0xFFFFFFFFu, (unsigned)qbin) + PAD0, NBIN - 1);
    SCAN_SPAN(S[blo], S[bhi + 1]);

    // expand until every lane's best beats the bin-edge bound on both sides
    while (true) {
        float gl = (q.x - (RANGE_LO + blo * BW)) * 0.9995f;  // slack: errs toward scanning
        float gr = ((RANGE_LO + (bhi + 1) * BW) - q.x) * 0.9995f;
        gl = fmaxf(gl, 0.f);
        gr = fmaxf(gr, 0.f);
        bool needL = (blo > 0) && (best > gl * gl);
        bool needR = (bhi < NBIN - 1) && (best > gr * gr);
        bool anyL = __any_sync(0xFFFFFFFFu, needL);
        bool anyR = __any_sync(0xFFFFFFFFu, needR);
        if (!anyL && !anyR) break;
        if (anyL) {
            int nblo = max(blo - CHUNK, 0);
            SCAN_SPAN(S[nblo], S[blo]);
            blo = nblo;
        }
        if (anyR) {
            int nbhi = min(bhi + CHUNK, NBIN - 1);
            SCAN_SPAN(S[bhi + 1], S[nbhi + 1]);
            bhi = nbhi;
        }
    }
#undef SCAN_SPAN

    // warp-sum NN distances -> one double atomic per warp (spread slots)
    float v = fmaxf(best, 0.f);
#pragma unroll
    for (int o = 16; o; o >>= 1) v += __shfl_down_sync(0xFFFFFFFFu, v, o);
    if (lane == 0)
        atomicAdd(&g_part[cloud][wq & (NSLOTS - 1)], (double)v);
}

// ---- final: loss = mean(dist1) + mean(dist2) ----
__global__ void final_kernel(float* __restrict__ out) {
    double s = 0.0;
    for (int i = 0; i < 2 * NSLOTS; i++) s += ((const double*)g_part)[i];
    out[0] = (float)(s * (1.0 / (double)(BB * NPTS)));
}

extern "C" void kernel_launch(void* const* d_in, const int* in_sizes, int n_in,
                              void* d_out, int out_size) {
    const float* pred = (const float*)d_in[0];
    const float* targ = (const float*)d_in[1];
    zero_kernel<<<(2 * BB * NBIN + 255) / 256, 256>>>();
    hist_kernel<<<(2 * BB * NPTS + 255) / 256, 256>>>(pred, targ);
    scan_kernel<<<16, NBIN>>>();
    scatter_kernel<<<(2 * BB * NPTS + 255) / 256, 256>>>(pred, targ);
    query_kernel<<<512, 256>>>();   // 4096 warps
    final_kernel<<<1, 1>>>((float*)d_out);
}

// round 17
// speedup vs baseline: 2.6626x; 2.6626x over previous
#include <cuda_runtime.h>
#include <cstdint>

typedef unsigned long long ull;

#define BB      8
#define NPTS    8192
#define NBIN    1024
#define RANGE_LO (-6.5f)
#define INV_BW   (NBIN / 13.0f)
#define NTILE   64            // pred tiles of 128 per (cloud,b)
#define TSZ     128
#define NCH     8             // query chunks of 1024 per (cloud,b)
#define TW      10            // tiles scanned per chunk: 8c-1 .. 8c+8
#define RM      8
#define NT      128

// ---- scratch (no allocations allowed) ----
__device__ float4   g_sx[2][BB][NPTS];        // x-sorted points (x,y,z,|p|^2)
__device__ unsigned g_bcnt[2][BB][NBIN];
__device__ unsigned g_bstart[2][BB][NBIN + 1];
__device__ unsigned g_bfill[2][BB][NBIN];
__device__ unsigned g_rm[2][BB][NPTS];        // row-mins (uint-ordered nonneg floats)
__device__ float    g_pref[2][BB][NTILE];     // prefix max of tile xmax
__device__ float    g_suff[2][BB][NTILE];     // suffix min of tile xmin
__device__ unsigned g_list[2 * BB * NPTS];
__device__ unsigned g_listn;

__device__ __forceinline__ int bin_of(float v) {
    int c = (int)((v - RANGE_LO) * INV_BW);
    return min(max(c, 0), NBIN - 1);
}
__device__ __forceinline__ ull splat2(float v) {
    ull r; asm("mov.b64 %0, {%1, %2};" : "=l"(r) : "f"(v), "f"(v)); return r;
}
__device__ __forceinline__ void unpack2(ull v, float& lo, float& hi) {
    asm("mov.b64 {%0, %1}, %2;" : "=f"(lo), "=f"(hi) : "l"(v));
}
#define FMA2(d, a, b, c) asm("fma.rn.f32x2 %0, %1, %2, %3;" : "=l"(d) : "l"(a), "l"(b), "l"(c))
#define ADD2(d, a, b)    asm("add.rn.f32x2 %0, %1, %2;"     : "=l"(d) : "l"(a), "l"(b))

// ---- zero ----
__global__ void zero_kernel() {
    int i = blockIdx.x * blockDim.x + threadIdx.x;
    if (i < 2 * BB * NBIN) { ((unsigned*)g_bcnt)[i] = 0u; ((unsigned*)g_bfill)[i] = 0u; }
    if (i < 2 * BB * NPTS) ((unsigned*)g_rm)[i] = 0x7F800000u;  // +inf
    if (i == 0) g_listn = 0u;
}

// ---- histogram over x-bins ----
__global__ void hist_kernel(const float* __restrict__ pred, const float* __restrict__ targ) {
    int i = blockIdx.x * blockDim.x + threadIdx.x;
    if (i >= 2 * BB * NPTS) return;
    int cloud = i / (BB * NPTS), rem = i - cloud * (BB * NPTS);
    const float* src = cloud ? targ : pred;
    atomicAdd(&g_bcnt[cloud][rem / NPTS][bin_of(src[3 * rem])], 1u);
}

// ---- exclusive scan over bins ----
__global__ void scan_kernel() {
    int cloud = blockIdx.x >> 3, b = blockIdx.x & 7, t = threadIdx.x;
    unsigned c = g_bcnt[cloud][b][t];
    __shared__ unsigned sh[NBIN];
    sh[t] = c; __syncthreads();
    for (int o = 1; o < NBIN; o <<= 1) {
        unsigned v = (t >= o) ? sh[t - o] : 0u;
        __syncthreads(); sh[t] += v; __syncthreads();
    }
    g_bstart[cloud][b][t] = sh[t] - c;
    if (t == NBIN - 1) g_bstart[cloud][b][NBIN] = sh[t];
}

// ---- scatter into x-sorted order (|p|^2 in w) ----
__global__ void scatter_kernel(const float* __restrict__ pred, const float* __restrict__ targ) {
    int i = blockIdx.x * blockDim.x + threadIdx.x;
    if (i >= 2 * BB * NPTS) return;
    int cloud = i / (BB * NPTS), rem = i - cloud * (BB * NPTS);
    const float* src = cloud ? targ : pred;
    float x = src[3 * rem], y = src[3 * rem + 1], z = src[3 * rem + 2];
    int b = rem / NPTS, bn = bin_of(x);
    unsigned pos = g_bstart[cloud][b][bn] + atomicAdd(&g_bfill[cloud][b][bn], 1u);
    g_sx[cloud][b][pos] = make_float4(x, y, z, x * x + y * y + z * z);
}

// ---- per-tile x min/max -> prefix max / suffix min ----
__global__ void minmax_kernel() {
    int cloud = blockIdx.x >> 3, b = blockIdx.x & 7, t = threadIdx.x;  // 64 threads
    __shared__ float smin[NTILE], smax[NTILE];
    float mn = INFINITY, mx = -INFINITY;
    const float4* P = g_sx[cloud][b] + t * TSZ;
    for (int i = 0; i < TSZ; i++) { float x = P[i].x; mn = fminf(mn, x); mx = fmaxf(mx, x); }
    smin[t] = mn; smax[t] = mx;
    __syncthreads();
    if (t == 0) {
        float pm = -INFINITY;
        for (int i = 0; i < NTILE; i++) { pm = fmaxf(pm, smax[i]); smax[i] = pm; }
        float sm = INFINITY;
        for (int i = NTILE - 1; i >= 0; i--) { sm = fminf(sm, smin[i]); smin[i] = sm; }
    }
    __syncthreads();
    g_pref[cloud][b][t] = smax[t];   // max x over tiles <= t
    g_suff[cloud][b][t] = smin[t];   // min x over tiles >= t
}

// ---- phase A: regular banded tiles (proven R6-style inner loop) ----
// block = (dir, b, chunk c of 1024 queries, tile slot tw in [0,TW)).
// Scans pred tile t = clamp(8c-1+tw) against the chunk: thread owns 8 queries
// (splat-packed constants), tile in pair-split smem, 64 broadcast j steps with
// fma.rn.f32x2, row-mins in registers -> global atomicMin. No col machinery.
__global__ void __launch_bounds__(NT) phaseA_kernel() {
    int id = blockIdx.x;
    int tw = id % TW; id /= TW;
    int c = id & 7, b = (id >> 3) & 7, dir = (id >> 6) & 1;
    int t = min(max(8 * c - 1 + tw, 0), NTILE - 1);
    const int tid = threadIdx.x;

    const float4* __restrict__ T = g_sx[dir][b] + c * 1024;         // queries
    const float4* __restrict__ P = g_sx[dir ^ 1][b] + t * TSZ;      // candidates

    ull axp[RM], ayp[RM], azp[RM], t2p[RM];
#pragma unroll
    for (int k = 0; k < RM; k++) {
        float4 q = T[k * NT + tid];
        axp[k] = splat2(-2.0f * q.x);
        ayp[k] = splat2(-2.0f * q.y);
        azp[k] = splat2(-2.0f * q.z);
        t2p[k] = splat2(q.w);
    }
    float rlo[RM], rhi[RM];
#pragma unroll
    for (int k = 0; k < RM; k++) { rlo[k] = INFINITY; rhi[k] = INFINITY; }

    __shared__ __align__(16) float s_px[TSZ], s_py[TSZ], s_pz[TSZ], s_pw[TSZ];
    {
        float4 p = P[tid];
        int i = tid & 63, h = tid >> 6;
        s_px[2 * i + h] = p.x; s_py[2 * i + h] = p.y;
        s_pz[2 * i + h] = p.z; s_pw[2 * i + h] = p.w;
    }
    __syncthreads();

#pragma unroll 8
    for (int j = 0; j < 64; j++) {
        ull pxp = *(const ull*)&s_px[2 * j];
        ull pyp = *(const ull*)&s_py[2 * j];
        ull pzp = *(const ull*)&s_pz[2 * j];
        ull pwp = *(const ull*)&s_pw[2 * j];
#pragma unroll
        for (int k = 0; k < RM; k++) {
            ull acc;
            ADD2(acc, pwp, t2p[k]);
            FMA2(acc, azp[k], pzp, acc);
            FMA2(acc, ayp[k], pyp, acc);
            FMA2(acc, axp[k], pxp, acc);
            float dlo, dhi;
            unpack2(acc, dlo, dhi);
            rlo[k] = fminf(rlo[k], dlo);
            rhi[k] = fminf(rhi[k], dhi);
        }
    }

#pragma unroll
    for (int k = 0; k < RM; k++) {
        float v = fmaxf(fminf(rlo[k], rhi[k]), 0.0f);   // clamp keeps uint order exact
        atomicMin(&g_rm[dir][b][c * 1024 + k * NT + tid], __float_as_uint(v));
    }
}

// ---- check: prove coverage or flag for brute fallback ----
// Unscanned left tiles (< 8c-1) have x <= pref[8c-2]; unscanned right tiles
// (> 8c+8) have x >= suff[8c+9]. If rowmin <= (0.999*gap)^2 the band answer
// is exact; otherwise the query goes to the exact brute list.
__global__ void check_kernel() {
    int i = blockIdx.x * blockDim.x + threadIdx.x;
    if (i >= 2 * BB * NPTS) return;
    int qidx = i & (NPTS - 1), b = (i >> 13) & 7, dir = i >> 16;
    float qx = g_sx[dir][b][qidx].x;
    float rm = __uint_as_float(g_rm[dir][b][qidx]);
    int c = qidx >> 10;
    float gap = INFINITY;
    int lt = 8 * c - 2;
    if (lt >= 0) gap = fminf(gap, qx - g_pref[dir ^ 1][b][lt]);
    int rt = 8 * c + 9;
    if (rt < NTILE) gap = fminf(gap, g_suff[dir ^ 1][b][rt] - qx);
    gap = fmaxf(gap, 0.0f) * 0.999f;
    if (!(rm <= gap * gap)) {
        unsigned pos = atomicAdd(&g_listn, 1u);
        g_list[pos] = (unsigned)i;
    }
}

// ---- phase B: exact brute force for flagged queries (warp per query) ----
__global__ void __launch_bounds__(256) phaseB_kernel() {
    int w0 = blockIdx.x * 8 + (threadIdx.x >> 5);
    int lane = threadIdx.x & 31;
    unsigned n = g_listn;
    for (unsigned w = w0; w < n; w += 16384) {
        unsigned e = g_list[w];
        int qidx = e & (NPTS - 1), b = (e >> 13) & 7, dir = e >> 16;
        float4 q = g_sx[dir][b][qidx];
        const float4* __restrict__ Pc = g_sx[dir ^ 1][b];
        float m2x = -2.f * q.x, m2y = -2.f * q.y, m2z = -2.f * q.z, qw = q.w;
        float best = INFINITY;
        for (int j = lane; j < NPTS; j += 32) {
            float4 p = Pc[j];
            best = fminf(best, fmaf(m2x, p.x, fmaf(m2y, p.y, fmaf(m2z, p.z, qw + p.w))));
        }
#pragma unroll
        for (int o = 16; o; o >>= 1) best = fminf(best, __shfl_xor_sync(0xFFFFFFFFu, best, o));
        if (lane == 0)
            atomicMin(&g_rm[dir][b][qidx], __float_as_uint(fmaxf(best, 0.0f)));
    }
}

// ---- final: loss = mean over both directions ----
__global__ void final_kernel(float* __restrict__ out) {
    __shared__ float sh[32];
    int tid = threadIdx.x;
    float s = 0.f;
    for (int i = tid; i < 2 * BB * NPTS; i += 1024)
        s += __uint_as_float(((const unsigned*)g_rm)[i]);
#pragma unroll
    for (int o = 16; o; o >>= 1) s += __shfl_down_sync(0xFFFFFFFFu, s, o);
    if ((tid & 31) == 0) sh[tid >> 5] = s;
    __syncthreads();
    if (tid < 32) {
        float v = sh[tid];
#pragma unroll
        for (int o = 16; o; o >>= 1) v += __shfl_down_sync(0xFFFFFFFFu, v, o);
        if (tid == 0) out[0] = v / (float)(BB * NPTS);
    }
}

extern "C" void kernel_launch(void* const* d_in, const int* in_sizes, int n_in,
                              void* d_out, int out_size) {
    const float* pred = (const float*)d_in[0];
    const float* targ = (const float*)d_in[1];
    zero_kernel<<<(2 * BB * NPTS + 255) / 256, 256>>>();
    hist_kernel<<<(2 * BB * NPTS + 255) / 256, 256>>>(pred, targ);
    scan_kernel<<<16, NBIN>>>();
    scatter_kernel<<<(2 * BB * NPTS + 255) / 256, 256>>>(pred, targ);
    minmax_kernel<<<16, NTILE>>>();
    phaseA_kernel<<<2 * BB * NCH * TW, NT>>>();            // 1280 regular tile blocks
    check_kernel<<<(2 * BB * NPTS + 255) / 256, 256>>>();
    phaseB_kernel<<<2048, 256>>>();
    final_kernel<<<1, 1024>>>((float*)d_out);
}